// round 3
// baseline (speedup 1.0000x reference)
#include <cuda_runtime.h>
#include <math_constants.h>

#define BATCH 4
#define SEQ   1024
#define DIM   1024
#define NH    16
#define HD    64
#define MROWS (BATCH*SEQ)   // 4096

// Scratch (static __device__ arrays: allowed; runtime alloc is not)
__device__ float g_qkv[(size_t)MROWS * 3 * DIM];   // 48 MB: [m][3*1024] = q|k|v
__device__ float g_y  [(size_t)MROWS * DIM];       // 16 MB: attention output [b*L+l][h*64+d]

// Swizzled float-index for a [rows][64] f32 tile stored row-major in 16B units:
// unit = row*16 + (g ^ ((row>>2)&15)), g = col/4. Conflict-free for both
// transposed stores (lanes vary row) and gemm loads (lanes vary g).
__device__ __forceinline__ int sw4(int row, int g) {
    return ((row << 4) + (g ^ ((row >> 2) & 15))) << 2;
}

// ---------------------------------------------------------------------------
// SGEMM: C[M,N] = A[M,K] * B[N,K]^T   (A row-major MxK, B row-major NxK)
// 128x128 block tile, BK=16, 256 threads, 8x8 microtile.
// Double-buffered smem: prefetch slab s+1 into registers while computing on
// slab s; one __syncthreads per K-step.
// ---------------------------------------------------------------------------
__global__ __launch_bounds__(256) void sgemm_tn(const float* __restrict__ A,
                                                const float* __restrict__ B,
                                                float* __restrict__ C,
                                                int M, int N, int K)
{
    __shared__ float As[2][16][128];
    __shared__ float Bs[2][16][128];

    const int tid = threadIdx.x;
    const int tx = tid & 15;        // 0..15 -> C col block
    const int ty = tid >> 4;        // 0..15 -> C row block
    const int lr = tid >> 2;        // 0..63 load row
    const int lv = tid & 3;         // 0..3  load float4 within 16-k slab

    const float* Ap = A + ((size_t)(blockIdx.y * 128 + lr)) * K + lv * 4;
    const float* Bp = B + ((size_t)(blockIdx.x * 128 + lr)) * K + lv * 4;

    float acc[8][8];
    #pragma unroll
    for (int i = 0; i < 8; i++)
        #pragma unroll
        for (int j = 0; j < 8; j++) acc[i][j] = 0.f;

    // prologue: load slab 0 into buffer 0
    {
        float4 a0 = *(const float4*)(Ap);
        float4 a1 = *(const float4*)(Ap + (size_t)64 * K);
        float4 b0 = *(const float4*)(Bp);
        float4 b1 = *(const float4*)(Bp + (size_t)64 * K);
        As[0][lv*4+0][lr]    = a0.x; As[0][lv*4+1][lr]    = a0.y;
        As[0][lv*4+2][lr]    = a0.z; As[0][lv*4+3][lr]    = a0.w;
        As[0][lv*4+0][lr+64] = a1.x; As[0][lv*4+1][lr+64] = a1.y;
        As[0][lv*4+2][lr+64] = a1.z; As[0][lv*4+3][lr+64] = a1.w;
        Bs[0][lv*4+0][lr]    = b0.x; Bs[0][lv*4+1][lr]    = b0.y;
        Bs[0][lv*4+2][lr]    = b0.z; Bs[0][lv*4+3][lr]    = b0.w;
        Bs[0][lv*4+0][lr+64] = b1.x; Bs[0][lv*4+1][lr+64] = b1.y;
        Bs[0][lv*4+2][lr+64] = b1.z; Bs[0][lv*4+3][lr+64] = b1.w;
    }
    __syncthreads();

    const int nsteps = K >> 4;
    for (int s = 0; s < nsteps; s++) {
        const int cur = s & 1;
        const bool has_next = (s + 1 < nsteps);

        // prefetch slab s+1 into registers (latency hidden under compute)
        float4 pa0, pa1, pb0, pb1;
        if (has_next) {
            int k0 = (s + 1) << 4;
            pa0 = *(const float4*)(Ap + k0);
            pa1 = *(const float4*)(Ap + (size_t)64 * K + k0);
            pb0 = *(const float4*)(Bp + k0);
            pb1 = *(const float4*)(Bp + (size_t)64 * K + k0);
        }

        #pragma unroll
        for (int kk = 0; kk < 16; kk++) {
            float a[8], b[8];
            *(float4*)&a[0] = *(const float4*)&As[cur][kk][ty*8];
            *(float4*)&a[4] = *(const float4*)&As[cur][kk][ty*8+4];
            *(float4*)&b[0] = *(const float4*)&Bs[cur][kk][tx*8];
            *(float4*)&b[4] = *(const float4*)&Bs[cur][kk][tx*8+4];
            #pragma unroll
            for (int i = 0; i < 8; i++)
                #pragma unroll
                for (int j = 0; j < 8; j++)
                    acc[i][j] = fmaf(a[i], b[j], acc[i][j]);
        }

        if (has_next) {
            // buffer cur^1 was last READ in step s-1; the barrier at the end
            // of step s-1 makes these stores safe.
            const int nxt = cur ^ 1;
            As[nxt][lv*4+0][lr]    = pa0.x; As[nxt][lv*4+1][lr]    = pa0.y;
            As[nxt][lv*4+2][lr]    = pa0.z; As[nxt][lv*4+3][lr]    = pa0.w;
            As[nxt][lv*4+0][lr+64] = pa1.x; As[nxt][lv*4+1][lr+64] = pa1.y;
            As[nxt][lv*4+2][lr+64] = pa1.z; As[nxt][lv*4+3][lr+64] = pa1.w;
            Bs[nxt][lv*4+0][lr]    = pb0.x; Bs[nxt][lv*4+1][lr]    = pb0.y;
            Bs[nxt][lv*4+2][lr]    = pb0.z; Bs[nxt][lv*4+3][lr]    = pb0.w;
            Bs[nxt][lv*4+0][lr+64] = pb1.x; Bs[nxt][lv*4+1][lr+64] = pb1.y;
            Bs[nxt][lv*4+2][lr+64] = pb1.z; Bs[nxt][lv*4+3][lr+64] = pb1.w;
            __syncthreads();
        }
    }

    float* Cp = C + ((size_t)(blockIdx.y * 128 + ty * 8)) * N + blockIdx.x * 128 + tx * 8;
    #pragma unroll
    for (int i = 0; i < 8; i++) {
        float4 c0 = make_float4(acc[i][0], acc[i][1], acc[i][2], acc[i][3]);
        float4 c1 = make_float4(acc[i][4], acc[i][5], acc[i][6], acc[i][7]);
        *(float4*)(Cp + (size_t)i * N)     = c0;
        *(float4*)(Cp + (size_t)i * N + 4) = c1;
    }
}

// ---------------------------------------------------------------------------
// Attention (flash style). Block = one (b,h) x 64-query tile.
// Qcat/Kcat = [x-path 64 dims | g-path 64 dims] -> K=128 for S.
// ---------------------------------------------------------------------------

// Load a logical 64(row) x 128(kk) tile TRANSPOSED into S[kk][row] (swizzled).
// x-path supplies kk 0..63 (stride ldx), g-path kk 64..127 (stride ldg).
__device__ __forceinline__ void load_qk_T(float* __restrict__ S,
                                          const float* __restrict__ srcX, int ldx,
                                          const float* __restrict__ srcG, int ldg,
                                          int tid)
{
    const int kg = tid >> 4;   // 0..15: row group (4 rows)
    const int vc = tid & 15;   // 0..15: float4 column within a 64-dim half
    #pragma unroll
    for (int half = 0; half < 2; half++) {
        const float* src = half ? srcG : srcX;
        const int ld = half ? ldg : ldx;
        float4 v[4];
        #pragma unroll
        for (int e = 0; e < 4; e++) {
            int r = kg * 4 + e;
            v[e] = *(const float4*)(src + (size_t)r * ld + vc * 4);
        }
        int kk = (vc + half * 16) * 4;
        *(float4*)(S + sw4(kk + 0, kg)) = make_float4(v[0].x, v[1].x, v[2].x, v[3].x);
        *(float4*)(S + sw4(kk + 1, kg)) = make_float4(v[0].y, v[1].y, v[2].y, v[3].y);
        *(float4*)(S + sw4(kk + 2, kg)) = make_float4(v[0].z, v[1].z, v[2].z, v[3].z);
        *(float4*)(S + sw4(kk + 3, kg)) = make_float4(v[0].w, v[1].w, v[2].w, v[3].w);
    }
}

// Load 64x64 V tile in natural [key][d] layout (swizzled).
__device__ __forceinline__ void load_v(float* __restrict__ SV,
                                       const float* __restrict__ srcV, int tid)
{
    #pragma unroll
    for (int it = 0; it < 4; it++) {
        int idx = tid + it * 256;
        int r = idx >> 4;      // key 0..63
        int g = idx & 15;      // float4 col
        *(float4*)(SV + sw4(r, g)) = *(const float4*)(srcV + (size_t)r * 3072 + g * 4);
    }
}

__global__ __launch_bounds__(256) void attn_kernel(const float* __restrict__ q_g,
                                                   const float* __restrict__ k_g,
                                                   float* __restrict__ y)
{
    extern __shared__ float sm[];
    float* SQ = sm;                // [128][64] f32 (kk-major, swizzled) 32KB
    float* SK = sm + 8192;         // [128][64]                          32KB
    float* SV = sm + 16384;        // [64][64]  (key-major)              16KB
    float* SP = sm + 20480;        // [64][64]  (key-major)              16KB

    const int tid = threadIdx.x;
    const int tx = tid & 15;       // key-block 0..15 (4 keys each)
    const int ty = tid >> 4;       // query-block 0..15 (4 queries each)
    const int bx = blockIdx.x;     // query tile 0..15
    const int bz = blockIdx.y;     // b*NH + h
    const int b = bz >> 4, h = bz & 15;

    // logits coeff: softmax((s_x+s_g)*1/sqrt(64) / ln(1024)), in log2 domain
    const float CLOG2 = 0.125f * 1.4426950408889634f / 6.9314718055994531f;

    // Load Qcat tile (persistent)
    {
        const float* srcX = g_qkv + ((size_t)(b * SEQ + bx * 64)) * 3072 + h * 64;
        const float* srcG = q_g   + ((size_t)(b * SEQ + bx * 64)) * DIM  + h * 64;
        load_qk_T(SQ, srcX, 3072, srcG, DIM, tid);
    }

    float m2[4], l[4], o[4][4];
    #pragma unroll
    for (int i = 0; i < 4; i++) {
        m2[i] = -CUDART_INF_F; l[i] = 0.f;
        #pragma unroll
        for (int j = 0; j < 4; j++) o[i][j] = 0.f;
    }

    for (int j = 0; j <= bx; j++) {
        __syncthreads();   // prior iteration's SK/SV/SP reads done (also covers SQ stores)
        {
            const float* srcX = g_qkv + ((size_t)(b * SEQ + j * 64)) * 3072 + 1024 + h * 64;
            const float* srcG = k_g   + ((size_t)(b * SEQ + j * 64)) * DIM  + h * 64;
            load_qk_T(SK, srcX, 3072, srcG, DIM, tid);
            const float* srcV = g_qkv + ((size_t)(b * SEQ + j * 64)) * 3072 + 2048 + h * 64;
            load_v(SV, srcV, tid);
        }
        __syncthreads();

        // S = Qcat · Kcatᵀ  (64x64, K=128)
        float s[4][4];
        #pragma unroll
        for (int i = 0; i < 4; i++)
            #pragma unroll
            for (int jj = 0; jj < 4; jj++) s[i][jj] = 0.f;

        #pragma unroll 8
        for (int kk = 0; kk < 128; kk++) {
            float4 aq = *(const float4*)(SQ + sw4(kk, ty));
            float4 bk = *(const float4*)(SK + sw4(kk, tx));
            float a[4] = {aq.x, aq.y, aq.z, aq.w};
            float c[4] = {bk.x, bk.y, bk.z, bk.w};
            #pragma unroll
            for (int i = 0; i < 4; i++)
                #pragma unroll
                for (int jj = 0; jj < 4; jj++)
                    s[i][jj] = fmaf(a[i], c[jj], s[i][jj]);
        }

        // scale to log2-logits + causal mask (tiles are aligned, only diag tile masks)
        const bool diag = (j == bx);
        #pragma unroll
        for (int i = 0; i < 4; i++)
            #pragma unroll
            for (int jj = 0; jj < 4; jj++) {
                float v = s[i][jj] * CLOG2;
                if (diag && (tx * 4 + jj > ty * 4 + i)) v = -CUDART_INF_F;
                s[i][jj] = v;
            }

        // online softmax over the 16 lanes sharing each row (tx dimension)
        #pragma unroll
        for (int i = 0; i < 4; i++) {
            float mt = fmaxf(fmaxf(s[i][0], s[i][1]), fmaxf(s[i][2], s[i][3]));
            #pragma unroll
            for (int off = 1; off < 16; off <<= 1)
                mt = fmaxf(mt, __shfl_xor_sync(0xffffffffu, mt, off));
            float mn = fmaxf(m2[i], mt);
            float al = exp2f(m2[i] - mn);
            m2[i] = mn;
            float r = 0.f;
            #pragma unroll
            for (int jj = 0; jj < 4; jj++) {
                float p = exp2f(s[i][jj] - mn);
                s[i][jj] = p;
                r += p;
            }
            #pragma unroll
            for (int off = 1; off < 16; off <<= 1)
                r += __shfl_xor_sync(0xffffffffu, r, off);
            l[i] = l[i] * al + r;
            #pragma unroll
            for (int jj = 0; jj < 4; jj++) o[i][jj] *= al;
        }

        // store P transposed into SP[key][qrow]
        #pragma unroll
        for (int jj = 0; jj < 4; jj++)
            *(float4*)(SP + sw4(tx * 4 + jj, ty)) =
                make_float4(s[0][jj], s[1][jj], s[2][jj], s[3][jj]);
        __syncthreads();

        // O += P · V  (64x64, K=64)
        #pragma unroll 8
        for (int kk = 0; kk < 64; kk++) {
            float4 pp = *(const float4*)(SP + sw4(kk, ty));
            float4 vv = *(const float4*)(SV + sw4(kk, tx));
            float p[4] = {pp.x, pp.y, pp.z, pp.w};
            float v[4] = {vv.x, vv.y, vv.z, vv.w};
            #pragma unroll
            for (int i = 0; i < 4; i++)
                #pragma unroll
                for (int jj = 0; jj < 4; jj++)
                    o[i][jj] = fmaf(p[i], v[jj], o[i][jj]);
        }
    }

    // epilogue: normalize and write y in [b*L+l][h*64+d] layout
    #pragma unroll
    for (int i = 0; i < 4; i++) {
        float inv = 1.0f / l[i];
        int qr = bx * 64 + ty * 4 + i;
        float4 out = make_float4(o[i][0] * inv, o[i][1] * inv,
                                 o[i][2] * inv, o[i][3] * inv);
        *(float4*)(y + ((size_t)(b * SEQ + qr)) * DIM + h * 64 + tx * 4) = out;
    }
}

// ---------------------------------------------------------------------------
extern "C" void kernel_launch(void* const* d_in, const int* in_sizes, int n_in,
                              void* d_out, int out_size)
{
    const float* x    = (const float*)d_in[0];   // [4,1024,1024]
    const float* q_g  = (const float*)d_in[1];   // [4,1024,1024]
    const float* k_g  = (const float*)d_in[2];   // [4,1024,1024]
    const float* Wqkv = (const float*)d_in[3];   // [3072,1024]
    const float* Wout = (const float*)d_in[4];   // [1024,1024]
    float* out = (float*)d_out;                  // [4,1024,1024]

    float* qkv_ptr = nullptr; float* y_ptr = nullptr;
    cudaGetSymbolAddress((void**)&qkv_ptr, g_qkv);
    cudaGetSymbolAddress((void**)&y_ptr,   g_y);

    // 1) qkv = x @ Wqkv^T   [4096,3072]
    sgemm_tn<<<dim3(3 * DIM / 128, MROWS / 128), 256>>>(x, Wqkv, qkv_ptr,
                                                        MROWS, 3 * DIM, DIM);

    // 2) attention -> y [4096,1024]
    static const int ATTN_SMEM = (8192 + 8192 + 4096 + 4096) * 4;  // 96 KB
    cudaFuncSetAttribute(attn_kernel, cudaFuncAttributeMaxDynamicSharedMemorySize, ATTN_SMEM);
    attn_kernel<<<dim3(SEQ / 64, BATCH * NH), 256, ATTN_SMEM>>>(q_g, k_g, y_ptr);

    // 3) out = y @ Wout^T   [4096,1024]
    sgemm_tn<<<dim3(DIM / 128, MROWS / 128), 256>>>(y_ptr, Wout, out,
                                                    MROWS, DIM, DIM);
}

// round 9
// speedup vs baseline: 1.3672x; 1.3672x over previous
#include <cuda_runtime.h>
#include <cuda_bf16.h>
#include <math_constants.h>
#include <cstdint>

#define BATCH 4
#define SEQ   1024
#define DIM   1024
#define NH    16
#define HD    64
#define MROWS (BATCH*SEQ)   // 4096

// Scratch (static __device__ arrays: allowed; runtime alloc is not)
__device__ float g_qkv[(size_t)MROWS * 3 * DIM];   // 48 MB
__device__ float g_y  [(size_t)MROWS * DIM];       // 16 MB

// ===========================================================================
// helpers
// ===========================================================================
__device__ __forceinline__ uint32_t smem_u32(const void* p) {
    uint32_t a;
    asm("{ .reg .u64 t; cvta.to.shared.u64 t, %1; cvt.u32.u64 %0, t; }"
        : "=r"(a) : "l"(p));
    return a;
}

// SW128-style 16B-granule swizzle on byte offsets within a 128B-row tile
__device__ __forceinline__ uint32_t swz(uint32_t x) { return x ^ ((x >> 3) & 0x70); }

#define LDSM_X4(d0, d1, d2, d3, adr) \
    asm volatile("ldmatrix.sync.aligned.m8n8.x4.shared.b16 {%0,%1,%2,%3}, [%4];" \
                 : "=r"(d0), "=r"(d1), "=r"(d2), "=r"(d3) : "r"(adr))

__device__ __forceinline__ void mma16816(float* c, const uint32_t* a,
                                         uint32_t b0, uint32_t b1) {
    asm volatile(
        "mma.sync.aligned.m16n8k16.row.col.f32.bf16.bf16.f32 "
        "{%0,%1,%2,%3}, {%4,%5,%6,%7}, {%8,%9}, {%0,%1,%2,%3};"
        : "+f"(c[0]), "+f"(c[1]), "+f"(c[2]), "+f"(c[3])
        : "r"(a[0]), "r"(a[1]), "r"(a[2]), "r"(a[3]), "r"(b0), "r"(b1));
}

// ===========================================================================
// Split-bf16 warp-MMA GEMM: C[M,N] = A[M,K] * B[N,K]^T (fp32 in/out)
// 128x128 tile, BK=64, 256 threads (8 warps, each 32x64).
// A,B split to bf16 hi+lo in smem; 3 mma terms: hi*hi + hi*lo + lo*hi.
// smem: 4 tiles x [128][64] bf16 (SW128 swizzled) = 64 KB.
// ===========================================================================
#define GT_K      64
#define TILE_B    16384
#define OFF_AHI   0
#define OFF_ALO   (1*TILE_B)
#define OFF_BHI   (2*TILE_B)
#define OFF_BLO   (3*TILE_B)
#define GEMM_SMEM (4*TILE_B)

// Load a 128row x 64col fp32 sub-tile, split to bf16 hi/lo, store swizzled.
// 256 threads: q = tid&7 (16B granule), r0 = tid>>3 (0..31), 4 row-iterations.
__device__ __forceinline__ void load_split_tile(const float* __restrict__ src, int ld,
                                                int k0, char* sh, char* sl,
                                                int q, int r0)
{
    #pragma unroll
    for (int it = 0; it < 4; it++) {
        int r = r0 + it * 32;
        const float4* p = (const float4*)(src + (size_t)r * ld + k0 + q * 8);
        float4 v0 = p[0], v1 = p[1];
        float f[8] = {v0.x, v0.y, v0.z, v0.w, v1.x, v1.y, v1.z, v1.w};
        uint32_t hw[4], lw[4];
        #pragma unroll
        for (int i = 0; i < 4; i++) {
            __nv_bfloat16 h0 = __float2bfloat16(f[2*i]);
            __nv_bfloat16 h1 = __float2bfloat16(f[2*i+1]);
            __nv_bfloat16 l0 = __float2bfloat16(f[2*i]   - __bfloat162float(h0));
            __nv_bfloat16 l1 = __float2bfloat16(f[2*i+1] - __bfloat162float(h1));
            __nv_bfloat162 hp; hp.x = h0; hp.y = h1;
            __nv_bfloat162 lp; lp.x = l0; lp.y = l1;
            hw[i] = *(uint32_t*)&hp;
            lw[i] = *(uint32_t*)&lp;
        }
        uint32_t off = swz((uint32_t)(r * 128 + q * 16));
        *(uint4*)(sh + off) = make_uint4(hw[0], hw[1], hw[2], hw[3]);
        *(uint4*)(sl + off) = make_uint4(lw[0], lw[1], lw[2], lw[3]);
    }
}

__global__ __launch_bounds__(256, 2)
void gemm_bf16x3(const float* __restrict__ A, const float* __restrict__ B,
                 float* __restrict__ C, int M, int N, int K)
{
    extern __shared__ __align__(1024) char sm[];
    const uint32_t sb = smem_u32(sm);
    const int tid  = threadIdx.x;
    const int lane = tid & 31;
    const int wid  = tid >> 5;
    const int wm   = wid & 3;    // m offset 32*wm
    const int wn   = wid >> 2;   // n offset 64*wn
    const int m0 = blockIdx.y * 128;
    const int n0 = blockIdx.x * 128;

    const int q  = tid & 7;
    const int r0 = tid >> 3;

    const float* Abase = A + (size_t)m0 * K;
    const float* Bbase = B + (size_t)n0 * K;

    float acc[2][8][4];
    #pragma unroll
    for (int mt = 0; mt < 2; mt++)
        #pragma unroll
        for (int nt = 0; nt < 8; nt++)
            #pragma unroll
            for (int e = 0; e < 4; e++) acc[mt][nt][e] = 0.f;

    // ldmatrix lane addressing (row within tile, 16B granule)
    const int lrA = wm * 32 + (lane & 15);        // + mt*16
    const int lrB = wn * 64 + (lane & 15);        // + nt2*16
    const int lg  = lane >> 4;                    // + ks*2

    const int nchunks = K / GT_K;
    for (int c = 0; c < nchunks; c++) {
        __syncthreads();   // previous chunk's smem reads complete
        load_split_tile(Abase, K, c * GT_K, sm + OFF_AHI, sm + OFF_ALO, q, r0);
        load_split_tile(Bbase, K, c * GT_K, sm + OFF_BHI, sm + OFF_BLO, q, r0);
        __syncthreads();

        // 3 terms: (Ahi,Bhi), (Ahi,Blo), (Alo,Bhi)
        #pragma unroll
        for (int term = 0; term < 3; term++) {
            const uint32_t aOff = sb + (term == 2 ? OFF_ALO : OFF_AHI);
            const uint32_t bOff = sb + (term == 1 ? OFF_BLO : OFF_BHI);
            #pragma unroll
            for (int ks = 0; ks < 4; ks++) {
                const int g = ks * 2 + lg;
                uint32_t a[2][4];
                #pragma unroll
                for (int mt = 0; mt < 2; mt++) {
                    uint32_t adr = aOff + swz((uint32_t)((lrA + mt*16) * 128 + g * 16));
                    LDSM_X4(a[mt][0], a[mt][1], a[mt][2], a[mt][3], adr);
                }
                #pragma unroll
                for (int nt2 = 0; nt2 < 4; nt2++) {
                    uint32_t b0, b1, b2, b3;
                    uint32_t adr = bOff + swz((uint32_t)((lrB + nt2*16) * 128 + g * 16));
                    LDSM_X4(b0, b1, b2, b3, adr);
                    // b0/b2 = n-tile (nt2*2), k0/k8 ; b1/b3 = n-tile (nt2*2+1)
                    #pragma unroll
                    for (int mt = 0; mt < 2; mt++) {
                        mma16816(acc[mt][nt2*2+0], a[mt], b0, b2);
                        mma16816(acc[mt][nt2*2+1], a[mt], b1, b3);
                    }
                }
            }
        }
    }

    // Epilogue: fragment c layout: c0,c1 -> row lane/4, cols 2*(lane%4)+{0,1};
    // c2,c3 -> row lane/4+8.
    const int rbase = m0 + wm * 32 + (lane >> 2);
    const int cbase = n0 + wn * 64 + (lane & 3) * 2;
    #pragma unroll
    for (int mt = 0; mt < 2; mt++) {
        #pragma unroll
        for (int nt = 0; nt < 8; nt++) {
            float* cp = C + (size_t)(rbase + mt * 16) * N + cbase + nt * 8;
            *(float2*)cp = make_float2(acc[mt][nt][0], acc[mt][nt][1]);
            *(float2*)(cp + (size_t)8 * N) = make_float2(acc[mt][nt][2], acc[mt][nt][3]);
        }
    }
}

// ===========================================================================
// Attention (flash style, fp32 SIMT) — unchanged from the passing R3 kernel.
// ===========================================================================
__device__ __forceinline__ int sw4(int row, int g) {
    return ((row << 4) + (g ^ ((row >> 2) & 15))) << 2;
}

__device__ __forceinline__ void load_qk_T(float* __restrict__ S,
                                          const float* __restrict__ srcX, int ldx,
                                          const float* __restrict__ srcG, int ldg,
                                          int tid)
{
    const int kg = tid >> 4;
    const int vc = tid & 15;
    #pragma unroll
    for (int half = 0; half < 2; half++) {
        const float* src = half ? srcG : srcX;
        const int ld = half ? ldg : ldx;
        float4 v[4];
        #pragma unroll
        for (int e = 0; e < 4; e++) {
            int r = kg * 4 + e;
            v[e] = *(const float4*)(src + (size_t)r * ld + vc * 4);
        }
        int kk = (vc + half * 16) * 4;
        *(float4*)(S + sw4(kk + 0, kg)) = make_float4(v[0].x, v[1].x, v[2].x, v[3].x);
        *(float4*)(S + sw4(kk + 1, kg)) = make_float4(v[0].y, v[1].y, v[2].y, v[3].y);
        *(float4*)(S + sw4(kk + 2, kg)) = make_float4(v[0].z, v[1].z, v[2].z, v[3].z);
        *(float4*)(S + sw4(kk + 3, kg)) = make_float4(v[0].w, v[1].w, v[2].w, v[3].w);
    }
}

__device__ __forceinline__ void load_v(float* __restrict__ SV,
                                       const float* __restrict__ srcV, int tid)
{
    #pragma unroll
    for (int it = 0; it < 4; it++) {
        int idx = tid + it * 256;
        int r = idx >> 4;
        int g = idx & 15;
        *(float4*)(SV + sw4(r, g)) = *(const float4*)(srcV + (size_t)r * 3072 + g * 4);
    }
}

__global__ __launch_bounds__(256) void attn_kernel(const float* __restrict__ q_g,
                                                   const float* __restrict__ k_g,
                                                   float* __restrict__ y)
{
    extern __shared__ float smf[];
    float* SQ = smf;
    float* SK = smf + 8192;
    float* SV = smf + 16384;
    float* SP = smf + 20480;

    const int tid = threadIdx.x;
    const int tx = tid & 15;
    const int ty = tid >> 4;
    const int bx = blockIdx.x;
    const int bz = blockIdx.y;
    const int b = bz >> 4, h = bz & 15;

    const float CLOG2 = 0.125f * 1.4426950408889634f / 6.9314718055994531f;

    {
        const float* srcX = g_qkv + ((size_t)(b * SEQ + bx * 64)) * 3072 + h * 64;
        const float* srcG = q_g   + ((size_t)(b * SEQ + bx * 64)) * DIM  + h * 64;
        load_qk_T(SQ, srcX, 3072, srcG, DIM, tid);
    }

    float m2[4], l[4], o[4][4];
    #pragma unroll
    for (int i = 0; i < 4; i++) {
        m2[i] = -CUDART_INF_F; l[i] = 0.f;
        #pragma unroll
        for (int j = 0; j < 4; j++) o[i][j] = 0.f;
    }

    for (int j = 0; j <= bx; j++) {
        __syncthreads();
        {
            const float* srcX = g_qkv + ((size_t)(b * SEQ + j * 64)) * 3072 + 1024 + h * 64;
            const float* srcG = k_g   + ((size_t)(b * SEQ + j * 64)) * DIM  + h * 64;
            load_qk_T(SK, srcX, 3072, srcG, DIM, tid);
            const float* srcV = g_qkv + ((size_t)(b * SEQ + j * 64)) * 3072 + 2048 + h * 64;
            load_v(SV, srcV, tid);
        }
        __syncthreads();

        float s[4][4];
        #pragma unroll
        for (int i = 0; i < 4; i++)
            #pragma unroll
            for (int jj = 0; jj < 4; jj++) s[i][jj] = 0.f;

        #pragma unroll 8
        for (int kk = 0; kk < 128; kk++) {
            float4 aq = *(const float4*)(SQ + sw4(kk, ty));
            float4 bk = *(const float4*)(SK + sw4(kk, tx));
            float a[4] = {aq.x, aq.y, aq.z, aq.w};
            float c[4] = {bk.x, bk.y, bk.z, bk.w};
            #pragma unroll
            for (int i = 0; i < 4; i++)
                #pragma unroll
                for (int jj = 0; jj < 4; jj++)
                    s[i][jj] = fmaf(a[i], c[jj], s[i][jj]);
        }

        const bool diag = (j == bx);
        #pragma unroll
        for (int i = 0; i < 4; i++)
            #pragma unroll
            for (int jj = 0; jj < 4; jj++) {
                float v = s[i][jj] * CLOG2;
                if (diag && (tx * 4 + jj > ty * 4 + i)) v = -CUDART_INF_F;
                s[i][jj] = v;
            }

        #pragma unroll
        for (int i = 0; i < 4; i++) {
            float mt = fmaxf(fmaxf(s[i][0], s[i][1]), fmaxf(s[i][2], s[i][3]));
            #pragma unroll
            for (int off = 1; off < 16; off <<= 1)
                mt = fmaxf(mt, __shfl_xor_sync(0xffffffffu, mt, off));
            float mn = fmaxf(m2[i], mt);
            float al = exp2f(m2[i] - mn);
            m2[i] = mn;
            float r = 0.f;
            #pragma unroll
            for (int jj = 0; jj < 4; jj++) {
                float p = exp2f(s[i][jj] - mn);
                s[i][jj] = p;
                r += p;
            }
            #pragma unroll
            for (int off = 1; off < 16; off <<= 1)
                r += __shfl_xor_sync(0xffffffffu, r, off);
            l[i] = l[i] * al + r;
            #pragma unroll
            for (int jj = 0; jj < 4; jj++) o[i][jj] *= al;
        }

        #pragma unroll
        for (int jj = 0; jj < 4; jj++)
            *(float4*)(SP + sw4(tx * 4 + jj, ty)) =
                make_float4(s[0][jj], s[1][jj], s[2][jj], s[3][jj]);
        __syncthreads();

        #pragma unroll 8
        for (int kk = 0; kk < 64; kk++) {
            float4 pp = *(const float4*)(SP + sw4(kk, ty));
            float4 vv = *(const float4*)(SV + sw4(kk, tx));
            float p[4] = {pp.x, pp.y, pp.z, pp.w};
            float v[4] = {vv.x, vv.y, vv.z, vv.w};
            #pragma unroll
            for (int i = 0; i < 4; i++)
                #pragma unroll
                for (int jj = 0; jj < 4; jj++)
                    o[i][jj] = fmaf(p[i], v[jj], o[i][jj]);
        }
    }

    #pragma unroll
    for (int i = 0; i < 4; i++) {
        float inv = 1.0f / l[i];
        int qr = bx * 64 + ty * 4 + i;
        float4 out = make_float4(o[i][0] * inv, o[i][1] * inv,
                                 o[i][2] * inv, o[i][3] * inv);
        *(float4*)(y + ((size_t)(b * SEQ + qr)) * DIM + h * 64 + tx * 4) = out;
    }
}

// ---------------------------------------------------------------------------
extern "C" void kernel_launch(void* const* d_in, const int* in_sizes, int n_in,
                              void* d_out, int out_size)
{
    const float* x    = (const float*)d_in[0];
    const float* q_g  = (const float*)d_in[1];
    const float* k_g  = (const float*)d_in[2];
    const float* Wqkv = (const float*)d_in[3];
    const float* Wout = (const float*)d_in[4];
    float* out = (float*)d_out;

    float* qkv_ptr = nullptr; float* y_ptr = nullptr;
    cudaGetSymbolAddress((void**)&qkv_ptr, g_qkv);
    cudaGetSymbolAddress((void**)&y_ptr,   g_y);

    cudaFuncSetAttribute(gemm_bf16x3, cudaFuncAttributeMaxDynamicSharedMemorySize, GEMM_SMEM);

    // 1) qkv = x @ Wqkv^T  [4096,3072]  (warp-MMA split-bf16)
    gemm_bf16x3<<<dim3(3 * DIM / 128, MROWS / 128), 256, GEMM_SMEM>>>(
        x, Wqkv, qkv_ptr, MROWS, 3 * DIM, DIM);

    // 2) attention -> y [4096,1024]
    static const int ATTN_SMEM = (8192 + 8192 + 4096 + 4096) * 4;  // 96 KB
    cudaFuncSetAttribute(attn_kernel, cudaFuncAttributeMaxDynamicSharedMemorySize, ATTN_SMEM);
    attn_kernel<<<dim3(SEQ / 64, BATCH * NH), 256, ATTN_SMEM>>>(q_g, k_g, y_ptr);

    // 3) out = y @ Wout^T  [4096,1024]  (warp-MMA split-bf16)
    gemm_bf16x3<<<dim3(DIM / 128, MROWS / 128), 256, GEMM_SMEM>>>(
        y_ptr, Wout, out, MROWS, DIM, DIM);
}